// round 10
// baseline (speedup 1.0000x reference)
#include <cuda_runtime.h>

// SpatialGraphConv fused kernel (fold-A-first, packed f32x2 FMA, persistent CTAs)
//
// out[n,c,t,w] = sum_{k,ci} W[k*128+c, ci] * xa[n,t,k,ci,w]  + sum_k b[k*128+c]*colsumA[k,w]
// where xa[n,t,k,ci,w] = sum_v x[n,ci,t,v] * effA[k,v,w],  effA = A*edge + adaptive_A
//
// One persistent CTA (128 threads) per SM. W (transposed), effA, bias live in
// smem for the whole kernel. Per tile (one n, 4 consecutive t):
//   1) stage X tile  2) fold A -> xa in smem  3) register-tiled GEMM
//   4) stage out tile in smem (reusing xa region)  5) coalesced writeback.

#define N_    64
#define CIN   64
#define T_    256
#define V_    25
#define K_    3
#define COUT  128
#define O_    384           // K_*COUT
#define KCI   192           // K_*CIN
#define TT    4             // t's per tile
#define NWP   13            // w pairs (w padded 25 -> 26)
#define THREADS 128
#define NTILES (N_ * (T_/TT))   // 4096

// ---- shared memory layout (float units) ----
#define WT_ROW 129
#define SM_WT   0
#define SM_WT_SZ (KCI*WT_ROW)                  // 24768
#define SM_XA   (SM_WT + SM_WT_SZ)             // u64[TT][KCI][NWP] = 9984 f2
#define XA_F2   (TT*KCI*NWP)
#define SM_XS   (SM_XA + 2*XA_F2)              // Xs[CIN][101]
#define XS_ROW  101
#define SM_XS_SZ (CIN*XS_ROW)                  // 6464
#define SM_EA   (SM_XS + SM_XS_SZ)             // effA2[K][V][NWP] f2
#define EA_F2   (K_*V_*NWP)                    // 975
#define SM_CS   (SM_EA + 2*EA_F2)              // colsum2[K][NWP] f2
#define CS_F2   (K_*NWP)                       // 39
#define SM_B    (SM_CS + 2*CS_F2)              // b[384]
#define SM_TOTAL_F (SM_B + O_)                 // 53612 floats
#define SMEM_BYTES (SM_TOTAL_F * 4)            // 214448 B  (< 227 KB limit)

typedef unsigned long long u64;

__device__ __forceinline__ u64 fma2(u64 a, u64 b, u64 c) {
    u64 d;
    asm("fma.rn.f32x2 %0, %1, %2, %3;" : "=l"(d) : "l"(a), "l"(b), "l"(c));
    return d;
}
__device__ __forceinline__ u64 pack2(float x, float y) {
    u64 d;
    asm("mov.b64 %0, {%1, %2};" : "=l"(d) : "f"(x), "f"(y));
    return d;
}
__device__ __forceinline__ float2 unpack2(u64 v) {
    float2 f;
    asm("mov.b64 {%0, %1}, %2;" : "=f"(f.x), "=f"(f.y) : "l"(v));
    return f;
}

extern __shared__ float smf[];

__global__ void __launch_bounds__(THREADS, 1)
sgc_kernel(const float* __restrict__ x, const float* __restrict__ Wg,
           const float* __restrict__ bg, const float* __restrict__ Ag,
           const float* __restrict__ eg, const float* __restrict__ dg,
           float* __restrict__ out)
{
    float* Wt = smf + SM_WT;                        // Wt[k*64+ci][c], row 129
    u64*   xa = (u64*)(smf + SM_XA);                // xa[tl][kci][wp]
    float* Xs = smf + SM_XS;                        // Xs[ci][tl*25+v], row 101
    u64*   eA = (u64*)(smf + SM_EA);                // effA2[k*V+v][wp]
    u64*   cs = (u64*)(smf + SM_CS);                // colsum2[k][wp]
    float* bs = smf + SM_B;

    const int tid = threadIdx.x;

    // ---- one-time setup (per persistent CTA) ----
    // W transposed: Wt[(o/128)*64 + ci][o%128] = W[o][ci]   (coalesced read,
    // conflict-free STS since row stride 129 % 32 == 1)
    for (int idx = tid; idx < O_ * CIN; idx += THREADS) {
        int o  = idx >> 6;
        int ci = idx & 63;
        Wt[((o >> 7) * 64 + ci) * WT_ROW + (o & 127)] = Wg[idx];
    }
    for (int i = tid; i < O_; i += THREADS) bs[i] = bg[i];
    for (int i = tid; i < EA_F2; i += THREADS) {
        int wp = i % NWP;
        int kv = i / NWP;                 // k*25 + v
        int w0 = 2 * wp;
        float e0 = Ag[kv*V_ + w0] * eg[kv*V_ + w0] + dg[kv*V_ + w0];
        float e1 = 0.f;
        if (w0 + 1 < V_) e1 = Ag[kv*V_ + w0+1] * eg[kv*V_ + w0+1] + dg[kv*V_ + w0+1];
        eA[i] = pack2(e0, e1);
    }
    __syncthreads();
    for (int i = tid; i < CS_F2; i += THREADS) {
        int k = i / NWP, wp = i % NWP;
        float sx = 0.f, sy = 0.f;
        for (int v = 0; v < V_; v++) {
            float2 t = unpack2(eA[(k*V_ + v)*NWP + wp]);
            sx += t.x; sy += t.y;
        }
        cs[i] = pack2(sx, sy);
    }
    __syncthreads();

    const int g     = tid >> 5;    // warp id == tl (0..3)
    const int cslot = tid & 31;

    for (int tile = blockIdx.x; tile < NTILES; tile += gridDim.x) {
        const int n  = tile >> 6;
        const int t0 = (tile & 63) * TT;

        // ---- 1) stage X tile: Xs[ci][tl*25+v] = x[n][ci][t0+tl][v] ----
        const float* xg = x + (long)n * CIN * T_ * V_ + (long)t0 * V_;
        for (int idx = tid; idx < CIN * TT * V_; idx += THREADS) {
            int ci = idx / (TT * V_);
            int r  = idx % (TT * V_);
            Xs[ci * XS_ROW + r] = xg[(long)ci * T_ * V_ + r];
        }
        __syncthreads();

        // ---- 2) fold A: xa[tl=g][k*64+ci][wp], ci in {cslot, cslot+32} ----
        for (int k = 0; k < K_; k++) {
            u64 acc[2][NWP];
            #pragma unroll
            for (int j = 0; j < 2; j++)
                #pragma unroll
                for (int wp = 0; wp < NWP; wp++) acc[j][wp] = 0ull;
            #pragma unroll 5
            for (int v = 0; v < V_; v++) {
                float x0 = Xs[cslot * XS_ROW + g * V_ + v];
                float x1 = Xs[(cslot + 32) * XS_ROW + g * V_ + v];
                u64 x0p = pack2(x0, x0);
                u64 x1p = pack2(x1, x1);
                const u64* ar = &eA[(k*V_ + v) * NWP];
                #pragma unroll
                for (int wp = 0; wp < NWP; wp++) {
                    u64 a2 = ar[wp];                     // warp-uniform broadcast
                    acc[0][wp] = fma2(x0p, a2, acc[0][wp]);
                    acc[1][wp] = fma2(x1p, a2, acc[1][wp]);
                }
            }
            #pragma unroll
            for (int wp = 0; wp < NWP; wp++) {
                xa[((g*KCI) + k*64 + cslot     ) * NWP + wp] = acc[0][wp];
                xa[((g*KCI) + k*64 + cslot + 32) * NWP + wp] = acc[1][wp];
            }
        }
        __syncthreads();

        // ---- 3) main GEMM: thread owns c in {cslot+32j}, tl=g, 13 w-pairs ----
        u64 oacc[4][NWP];
        #pragma unroll
        for (int j = 0; j < 4; j++) {
            const int c = cslot + 32 * j;
            #pragma unroll
            for (int wp = 0; wp < NWP; wp++) oacc[j][wp] = 0ull;
            #pragma unroll
            for (int k = 0; k < K_; k++) {
                float bv = bs[k * COUT + c];
                u64 bp = pack2(bv, bv);
                #pragma unroll
                for (int wp = 0; wp < NWP; wp++)
                    oacc[j][wp] = fma2(bp, cs[k*NWP + wp], oacc[j][wp]);
            }
        }
        const u64* xrow = &xa[(long)g * KCI * NWP];
        #pragma unroll 2
        for (int kci = 0; kci < KCI; kci++) {
            const float* wr = &Wt[kci * WT_ROW + cslot];
            u64 w0 = pack2(wr[0],  wr[0]);
            u64 w1 = pack2(wr[32], wr[32]);
            u64 w2 = pack2(wr[64], wr[64]);
            u64 w3 = pack2(wr[96], wr[96]);
            const u64* xr = &xrow[kci * NWP];
            #pragma unroll
            for (int wp = 0; wp < NWP; wp++) {
                u64 xv = xr[wp];                          // warp-uniform broadcast
                oacc[0][wp] = fma2(w0, xv, oacc[0][wp]);
                oacc[1][wp] = fma2(w1, xv, oacc[1][wp]);
                oacc[2][wp] = fma2(w2, xv, oacc[2][wp]);
                oacc[3][wp] = fma2(w3, xv, oacc[3][wp]);
            }
        }
        __syncthreads();   // everyone done reading xa -> reuse region as out stage

        // ---- 4) stage out tile: os[c][tl*25+w], row 101 (conflict-free) ----
        float* os = (float*)xa;    // needs 128*101 = 12928 floats (<= 19968)
        #pragma unroll
        for (int j = 0; j < 4; j++) {
            const int c = cslot + 32 * j;
            float* row = &os[c * 101 + g * V_];
            #pragma unroll
            for (int wp = 0; wp < NWP; wp++) {
                float2 t = unpack2(oacc[j][wp]);
                int w0i = 2 * wp;
                row[w0i] = t.x;
                if (w0i + 1 < V_) row[w0i + 1] = t.y;
            }
        }
        __syncthreads();

        // ---- 5) coalesced writeback: out[n][c][t0+tl][w] ----
        float* og = out + (long)n * COUT * T_ * V_ + (long)t0 * V_;
        for (int idx = tid; idx < COUT * TT * V_; idx += THREADS) {
            int c = idx / (TT * V_);
            int r = idx % (TT * V_);
            og[(long)c * T_ * V_ + r] = os[c * 101 + r];
        }
        __syncthreads();   // protect xa/Xs before next tile
    }
}

extern "C" void kernel_launch(void* const* d_in, const int* in_sizes, int n_in,
                              void* d_out, int out_size)
{
    (void)in_sizes; (void)n_in; (void)out_size;
    const float* x    = (const float*)d_in[0];
    const float* W    = (const float*)d_in[1];
    const float* b    = (const float*)d_in[2];
    const float* A    = (const float*)d_in[3];
    const float* edge = (const float*)d_in[4];
    const float* adp  = (const float*)d_in[5];
    float* out = (float*)d_out;

    int dev = 0, nsm = 0;
    cudaGetDevice(&dev);
    cudaDeviceGetAttribute(&nsm, cudaDevAttrMultiProcessorCount, dev);
    if (nsm <= 0) nsm = 148;
    cudaFuncSetAttribute(sgc_kernel,
                         cudaFuncAttributeMaxDynamicSharedMemorySize, SMEM_BYTES);

    sgc_kernel<<<nsm, THREADS, SMEM_BYTES>>>(x, W, b, A, edge, adp, out);
}